// round 12
// baseline (speedup 1.0000x reference)
#include <cuda_runtime.h>
#include <math.h>

typedef unsigned long long ull;

#define BB 64
#define NN 4096
#define DD 128
#define SS 7
#define HH 128
#define MM 256
#define TROWS 64
#define LN_EPS 1e-5f
#define EPSF 1e-8f
#define SCALE 0.08838834764831845f   // 128^-0.5

// ---------------- device scratch ----------------
__device__ __align__(16) float g_slots[BB*SS*HH];
__device__ __align__(16) float g_u[BB*SS*DD];     // folded: SCALE*g*qk - e/128
__device__ float g_c[BB*SS];
__device__ __align__(16) float g_acc[BB*SS*DD];   // sum_n as*x
__device__ float g_sumWM[BB*SS];                  // sum_n as*m
__device__ float g_W[BB*SS];                      // sum_n ws
__device__ __align__(16) float g_upd[BB*SS*HH];
__device__ __align__(16) float g_gi[BB*SS*3*HH];
__device__ __align__(16) float g_gh[BB*SS*3*HH];
__device__ __align__(16) float g_smid[BB*SS*HH];
__device__ __align__(16) float g_hid[BB*SS*MM];

// ---------------- packed f32x2 helpers ----------------
static __device__ __forceinline__ ull pk2(float lo, float hi) {
    ull r; asm("mov.b64 %0,{%1,%2};" : "=l"(r) : "f"(lo), "f"(hi)); return r;
}
static __device__ __forceinline__ void upk2(float& lo, float& hi, ull v) {
    asm("mov.b64 {%0,%1},%2;" : "=f"(lo), "=f"(hi) : "l"(v));
}
static __device__ __forceinline__ ull ffma2(ull a, ull b, ull c) {
    ull d; asm("fma.rn.f32x2 %0,%1,%2,%3;" : "=l"(d) : "l"(a), "l"(b), "l"(c)); return d;
}
static __device__ __forceinline__ ull fadd2(ull a, ull b) {
    ull d; asm("add.rn.f32x2 %0,%1,%2;" : "=l"(d) : "l"(a), "l"(b)); return d;
}
static __device__ __forceinline__ float hsum2(ull v) {
    float lo, hi; upk2(lo, hi, v); return lo + hi;
}
static __device__ __forceinline__ float dot4(float4 a, float4 b) {
    return a.x*b.x + a.y*b.y + a.z*b.z + a.w*b.w;
}

// ---------------- prep (device): slot LN -> q -> qk -> u~,c; zero accs ----
static __device__ void prep_dev(
    int b, int tid,
    const float* slots_sm,
    float* sn, float* q, float* red,
    const float* __restrict__ ln_s_g, const float* __restrict__ ln_s_b,
    const float* __restrict__ ln_in_g, const float* __restrict__ ln_in_b,
    const float* __restrict__ Wq, const float* __restrict__ Wk)
{
    int wid = tid >> 5, lane = tid & 31;
    if (tid < 16) red[tid] = 0.f;
    __syncthreads();

    if (tid < 128) {
        for (int s = wid; s < SS; s += 4) {
            float4 x = *(const float4*)&slots_sm[s*HH + lane*4];
            float sm = x.x+x.y+x.z+x.w;
            float sq = dot4(x, x);
            #pragma unroll
            for (int o = 16; o; o >>= 1) {
                sm += __shfl_xor_sync(0xffffffffu, sm, o);
                sq += __shfl_xor_sync(0xffffffffu, sq, o);
            }
            float m   = sm * (1.f/HH);
            float inv = rsqrtf(sq*(1.f/HH) - m*m + LN_EPS);
            int d = lane*4;
            sn[s*HH+d+0] = (x.x-m)*inv*ln_s_g[d+0] + ln_s_b[d+0];
            sn[s*HH+d+1] = (x.y-m)*inv*ln_s_g[d+1] + ln_s_b[d+1];
            sn[s*HH+d+2] = (x.z-m)*inv*ln_s_g[d+2] + ln_s_b[d+2];
            sn[s*HH+d+3] = (x.w-m)*inv*ln_s_g[d+3] + ln_s_b[d+3];
        }
    }
    __syncthreads();

    // q[s][h] = sn[s] . Wq[h]
    if (tid < 128) {
        int h = tid;
        float a[SS];
        #pragma unroll
        for (int s = 0; s < SS; s++) a[s] = 0.f;
        const float4* wr = (const float4*)(Wq + h*HH);
        for (int k = 0; k < HH/4; k++) {
            float4 w = __ldg(&wr[k]);
            #pragma unroll
            for (int s = 0; s < SS; s++)
                a[s] += dot4(w, *(const float4*)&sn[s*HH + k*4]);
        }
        #pragma unroll
        for (int s = 0; s < SS; s++) q[s*HH+h] = a[s];
    }
    __syncthreads();

    float acc[SS];
    if (tid < 128) {
        int d = tid;
        #pragma unroll
        for (int s = 0; s < SS; s++) acc[s] = 0.f;
        for (int h4 = 0; h4 < HH/4; h4++) {
            float w0 = __ldg(&Wk[(h4*4+0)*HH + d]);
            float w1 = __ldg(&Wk[(h4*4+1)*HH + d]);
            float w2 = __ldg(&Wk[(h4*4+2)*HH + d]);
            float w3 = __ldg(&Wk[(h4*4+3)*HH + d]);
            #pragma unroll
            for (int s = 0; s < SS; s++) {
                float4 qv = *(const float4*)&q[s*HH + h4*4];
                acc[s] += qv.x*w0 + qv.y*w1 + qv.z*w2 + qv.w*w3;
            }
        }
        float gg  = ln_in_g[d];
        float bbv = ln_in_b[d];
        float pe[SS], pc[SS];
        #pragma unroll
        for (int s = 0; s < SS; s++) {
            pe[s] = SCALE * gg  * acc[s];
            pc[s] = SCALE * bbv * acc[s];
        }
        #pragma unroll
        for (int o = 16; o; o >>= 1) {
            #pragma unroll
            for (int s = 0; s < SS; s++) {
                pe[s] += __shfl_xor_sync(0xffffffffu, pe[s], o);
                pc[s] += __shfl_xor_sync(0xffffffffu, pc[s], o);
            }
        }
        if (lane == 0) {
            #pragma unroll
            for (int s = 0; s < SS; s++) {
                atomicAdd(&red[s],   pe[s]);
                atomicAdd(&red[8+s], pc[s]);
            }
        }
    }
    __syncthreads();

    if (tid < 128) {
        int d = tid;
        float gg = ln_in_g[d];
        #pragma unroll
        for (int s = 0; s < SS; s++)
            g_u[(b*SS+s)*DD + d] = SCALE*gg*acc[s] - red[s]*(1.f/DD);
    }
    if (tid < SS) {
        g_c[b*SS+tid]     = red[8+tid];
        g_W[b*SS+tid]     = 0.f;
        g_sumWM[b*SS+tid] = 0.f;
    }
    for (int i = tid; i < SS*DD; i += blockDim.x) g_acc[b*SS*DD + i] = 0.f;
}

// ---------------- init + first prep ----------------
__global__ void __launch_bounds__(128) k_init0(
    const float* __restrict__ sinit,
    const float* __restrict__ mu,
    const float* __restrict__ lsig,
    const float* __restrict__ ln_s_g, const float* __restrict__ ln_s_b,
    const float* __restrict__ ln_in_g, const float* __restrict__ ln_in_b,
    const float* __restrict__ Wq, const float* __restrict__ Wk)
{
    __shared__ __align__(16) float T[896*3];
    __shared__ float red[16];
    int b = blockIdx.x, tid = threadIdx.x;
    for (int i = tid; i < SS*HH; i += 128) {
        int s = i >> 7, h = i & 127;
        float v = mu[h] + expf(lsig[h]) * sinit[(b*SS+s)*(HH+4) + h];
        T[i] = v;
        g_slots[b*SS*HH + i] = v;
    }
    __syncthreads();
    prep_dev(b, tid, T, T+896, T+1792, red,
             ln_s_g, ln_s_b, ln_in_g, ln_in_b, Wq, Wk);
}

// ---------------- streaming pass: 64-row tile, half-row per thread -------
// layout: row stride 132 floats; cols 0..63 at +0, cols 64..127 at +68
__global__ void __launch_bounds__(128) k_pass(const float* __restrict__ inputs)
{
    __shared__ __align__(16) float tile[TROWS*132];   // 33792 B
    __shared__ __align__(16) float ubuf[896];
    __shared__ __align__(16) ull   wbuf[TROWS*8];
    __shared__ float sAW[SS], sAM[SS];
    int b = blockIdx.y, chunk = blockIdx.x;
    int tid = threadIdx.x, wid = tid >> 5, lane = tid & 31;

    for (int i = tid; i < 224; i += 128)
        ((float4*)ubuf)[i] = ((const float4*)(g_u + b*SS*DD))[i];
    if (tid < 2*SS) { if (tid < SS) sAW[tid] = 0.f; else sAM[tid-SS] = 0.f; }

    const float4* gin = (const float4*)(inputs + ((size_t)b*NN + (size_t)chunk*TROWS)*DD);
    #pragma unroll
    for (int j = 0; j < TROWS*32/128; j++) {
        int i = tid + j*128;
        int r = i >> 5, c = i & 31;
        int off = c*4 + ((c >> 4) << 2);      // 0..60 , 68..128
        *(float4*)&tile[r*132 + off] = __ldg(&gin[i]);
    }
    __syncthreads();

    // pass 1: thread = (row, half); 16 chunks of 4 floats
    {
        int row = tid >> 1, half = tid & 1;
        const float* xr = tile + row*132 + half*68;
        const float* ur = ubuf + half*64;
        ull d2[SS], sm2 = 0ull, sq2 = 0ull;
        #pragma unroll
        for (int s = 0; s < SS; s++) d2[s] = 0ull;
        #pragma unroll 4
        for (int k = 0; k < 16; k++) {
            ulonglong2 x = *(const ulonglong2*)(xr + k*4);
            sm2 = fadd2(sm2, fadd2(x.x, x.y));
            sq2 = ffma2(x.x, x.x, ffma2(x.y, x.y, sq2));
            #pragma unroll
            for (int s = 0; s < SS; s++) {
                ulonglong2 u = *(const ulonglong2*)(ur + s*128 + k*4);
                d2[s] = ffma2(x.x, u.x, ffma2(x.y, u.y, d2[s]));
            }
        }
        float p[SS+2];
        #pragma unroll
        for (int s = 0; s < SS; s++) p[s] = hsum2(d2[s]);
        p[SS]   = hsum2(sm2);
        p[SS+1] = hsum2(sq2);
        #pragma unroll
        for (int j = 0; j < SS+2; j++)
            p[j] += __shfl_xor_sync(0xffffffffu, p[j], 1);

        float m   = p[SS] * (1.f/DD);
        float inv = rsqrtf(p[SS+1]*(1.f/DD) - m*m + LN_EPS);
        float lg[SS], mx = -1e30f;
        #pragma unroll
        for (int s = 0; s < SS; s++) {
            lg[s] = p[s]*inv + __ldg(&g_c[b*SS+s]);
            mx = fmaxf(mx, lg[s]);
        }
        float e[SS], sum = 0.f;
        #pragma unroll
        for (int s = 0; s < SS; s++) { e[s] = __expf(lg[s]-mx); sum += e[s]; }
        float isum = __fdividef(1.f, sum);
        float pw[SS], pm[SS];
        #pragma unroll
        for (int s = 0; s < SS; s++) {
            float ws = e[s]*isum + EPSF;
            float as = ws*inv;
            if (half == 0) wbuf[row*8+s] = pk2(as, as);
            pw[s] = ws;
            pm[s] = as*m;
        }
        // warp-sum (each row counted twice -> *0.5)
        #pragma unroll
        for (int o = 16; o; o >>= 1) {
            #pragma unroll
            for (int s = 0; s < SS; s++) {
                pw[s] += __shfl_xor_sync(0xffffffffu, pw[s], o);
                pm[s] += __shfl_xor_sync(0xffffffffu, pm[s], o);
            }
        }
        if (lane == 0) {
            #pragma unroll
            for (int s = 0; s < SS; s++) {
                atomicAdd(&sAW[s], pw[s]*0.5f);
                atomicAdd(&sAM[s], pm[s]*0.5f);
            }
        }
    }
    __syncthreads();

    // pass 2: warp per 16 rows, lane = 4-float column slice
    ull a0[SS], a1[SS];
    #pragma unroll
    for (int s = 0; s < SS; s++) { a0[s] = 0ull; a1[s] = 0ull; }
    {
        int xo = lane*4 + ((lane >> 4) << 2);
        int r0 = wid*16;
        #pragma unroll 4
        for (int i = 0; i < 16; i++) {
            int r = r0 + i;
            ulonglong2 x = *(const ulonglong2*)&tile[r*132 + xo];
            #pragma unroll
            for (int s = 0; s < SS; s++) {
                ull w = wbuf[r*8+s];
                a0[s] = ffma2(x.x, w, a0[s]);
                a1[s] = ffma2(x.y, w, a1[s]);
            }
        }
    }
    __syncthreads();            // tile reads done
    float* red = tile;          // reuse: [4][7][128]
    #pragma unroll
    for (int s = 0; s < SS; s++) {
        float4 v;
        upk2(v.x, v.y, a0[s]);
        upk2(v.z, v.w, a1[s]);
        *(float4*)&red[(wid*SS+s)*128 + lane*4] = v;
    }
    __syncthreads();
    // FIX R9: 224 work items must loop over a 128-thread block (was tid<224)
    for (int t = tid; t < SS*32; t += 128) {
        int s = t >> 5, l = t & 31;
        float4 v = *(const float4*)&red[s*128 + l*4];
        #pragma unroll
        for (int w = 1; w < 4; w++) {
            float4 r4 = *(const float4*)&red[(w*SS+s)*128 + l*4];
            v.x += r4.x; v.y += r4.y; v.z += r4.z; v.w += r4.w;
        }
        float* dst = &g_acc[(b*SS+s)*DD + l*4];
        atomicAdd(dst+0, v.x); atomicAdd(dst+1, v.y);
        atomicAdd(dst+2, v.z); atomicAdd(dst+3, v.w);
    }
    if (tid < 2*SS) {
        if (tid < SS) atomicAdd(&g_W[b*SS+tid],        sAW[tid]);
        else          atomicAdd(&g_sumWM[b*SS+tid-SS], sAM[tid-SS]);
    }
}

// ---------------- kU1: z=0 -> y + Wv ; z=1..3 -> gh tiles ----------------
__global__ void __launch_bounds__(128) k_u1(
    const float* __restrict__ ln_in_g, const float* __restrict__ ln_in_b,
    const float* __restrict__ Wv, const float* __restrict__ W_hh,
    const float* __restrict__ b_hh)
{
    __shared__ __align__(16) float X[SS*HH];
    __shared__ float Ws[SS], SWM[SS];
    int b = blockIdx.x, z = blockIdx.y, tid = threadIdx.x;

    if (z == 0) {
        if (tid < SS) { Ws[tid] = g_W[b*SS+tid]; SWM[tid] = g_sumWM[b*SS+tid]; }
        __syncthreads();
        for (int i = tid; i < SS*DD; i += 128) {
            int s = i >> 7, d = i & 127;
            float wv = Ws[s];
            X[i] = (ln_in_g[d]*(g_acc[b*SS*DD+i] - SWM[s]) + ln_in_b[d]*wv)
                   * __fdividef(1.f, wv);
        }
        __syncthreads();
        int h = tid;
        ull a[SS];
        #pragma unroll
        for (int s = 0; s < SS; s++) a[s] = 0ull;
        for (int k = 0; k < 32; k++) {
            ulonglong2 w = __ldg((const ulonglong2*)(Wv + h*DD + k*4));
            #pragma unroll
            for (int s = 0; s < SS; s++) {
                ulonglong2 xv = *(const ulonglong2*)&X[s*HH + k*4];
                a[s] = ffma2(w.x, xv.x, ffma2(w.y, xv.y, a[s]));
            }
        }
        #pragma unroll
        for (int s = 0; s < SS; s++) g_upd[(b*SS+s)*HH + h] = hsum2(a[s]);
    } else {
        for (int i = tid; i < SS*HH; i += 128) X[i] = g_slots[b*SS*HH + i];
        __syncthreads();
        int r = (z-1)*128 + tid;
        ull a[SS];
        #pragma unroll
        for (int s = 0; s < SS; s++) a[s] = 0ull;
        for (int k = 0; k < 32; k++) {
            ulonglong2 w = __ldg((const ulonglong2*)(W_hh + r*HH + k*4));
            #pragma unroll
            for (int s = 0; s < SS; s++) {
                ulonglong2 xv = *(const ulonglong2*)&X[s*HH + k*4];
                a[s] = ffma2(w.x, xv.x, ffma2(w.y, xv.y, a[s]));
            }
        }
        float bias = b_hh[r];
        #pragma unroll
        for (int s = 0; s < SS; s++) g_gh[(b*SS+s)*384 + r] = hsum2(a[s]) + bias;
    }
}

// ---------------- kU2: gi tiles ----------------
__global__ void __launch_bounds__(128) k_u2(
    const float* __restrict__ W_ih, const float* __restrict__ b_ih)
{
    __shared__ __align__(16) float X[SS*HH];
    int b = blockIdx.x, z = blockIdx.y, tid = threadIdx.x;
    for (int i = tid; i < SS*HH; i += 128) X[i] = g_upd[b*SS*HH + i];
    __syncthreads();
    int r = z*128 + tid;
    ull a[SS];
    #pragma unroll
    for (int s = 0; s < SS; s++) a[s] = 0ull;
    for (int k = 0; k < 32; k++) {
        ulonglong2 w = __ldg((const ulonglong2*)(W_ih + r*HH + k*4));
        #pragma unroll
        for (int s = 0; s < SS; s++) {
            ulonglong2 xv = *(const ulonglong2*)&X[s*HH + k*4];
            a[s] = ffma2(w.x, xv.x, ffma2(w.y, xv.y, a[s]));
        }
    }
    float bias = b_ih[r];
    #pragma unroll
    for (int s = 0; s < SS; s++) g_gi[(b*SS+s)*384 + r] = hsum2(a[s]) + bias;
}

// ---------------- kU3: GRU + LN + MLP1 tiles ----------------
__global__ void __launch_bounds__(128) k_u3(
    const float* __restrict__ ln_m_g, const float* __restrict__ ln_m_b,
    const float* __restrict__ w1, const float* __restrict__ b1)
{
    __shared__ __align__(16) float SM[SS*HH];
    __shared__ __align__(16) float SN[SS*HH];
    int b = blockIdx.x, z = blockIdx.y, tid = threadIdx.x;
    int wid = tid >> 5, lane = tid & 31;

    for (int i = tid; i < SS*HH; i += 128) {
        int s = i >> 7, h = i & 127;
        const float* gi = g_gi + (b*SS+s)*384;
        const float* gh = g_gh + (b*SS+s)*384;
        float rr = 1.f/(1.f + __expf(-(gi[h]       + gh[h])));
        float zz = 1.f/(1.f + __expf(-(gi[128+h]   + gh[128+h])));
        float nn = tanhf(gi[256+h] + rr*gh[256+h]);
        float v  = (1.f - zz)*nn + zz*g_slots[b*SS*HH + i];
        SM[i] = v;
        if (z == 0) g_smid[b*SS*HH + i] = v;
    }
    __syncthreads();

    for (int s = wid; s < SS; s += 4) {
        float4 x = *(const float4*)&SM[s*HH + lane*4];
        float sm = x.x+x.y+x.z+x.w;
        float sq = dot4(x, x);
        #pragma unroll
        for (int o = 16; o; o >>= 1) {
            sm += __shfl_xor_sync(0xffffffffu, sm, o);
            sq += __shfl_xor_sync(0xffffffffu, sq, o);
        }
        float m   = sm * (1.f/HH);
        float inv = rsqrtf(sq*(1.f/HH) - m*m + LN_EPS);
        int d = lane*4;
        SN[s*HH+d+0] = (x.x-m)*inv*ln_m_g[d+0] + ln_m_b[d+0];
        SN[s*HH+d+1] = (x.y-m)*inv*ln_m_g[d+1] + ln_m_b[d+1];
        SN[s*HH+d+2] = (x.z-m)*inv*ln_m_g[d+2] + ln_m_b[d+2];
        SN[s*HH+d+3] = (x.w-m)*inv*ln_m_g[d+3] + ln_m_b[d+3];
    }
    __syncthreads();

    int j = z*128 + tid;
    ull a[SS];
    #pragma unroll
    for (int s = 0; s < SS; s++) a[s] = 0ull;
    for (int k = 0; k < 32; k++) {
        ulonglong2 w = __ldg((const ulonglong2*)(w1 + j*HH + k*4));
        #pragma unroll
        for (int s = 0; s < SS; s++) {
            ulonglong2 xv = *(const ulonglong2*)&SN[s*HH + k*4];
            a[s] = ffma2(w.x, xv.x, ffma2(w.y, xv.y, a[s]));
        }
    }
    float bb = b1[j];
    #pragma unroll
    for (int s = 0; s < SS; s++)
        g_hid[(b*SS+s)*MM + j] = fmaxf(hsum2(a[s]) + bb, 0.f);
}

// ---------------- kU4: MLP2 + residual + write out + prep ---------------
__global__ void __launch_bounds__(256) k_u4(
    const float* __restrict__ ln_s_g, const float* __restrict__ ln_s_b,
    const float* __restrict__ ln_in_g, const float* __restrict__ ln_in_b,
    const float* __restrict__ Wq, const float* __restrict__ Wk,
    const float* __restrict__ w2, const float* __restrict__ b2,
    float* __restrict__ out)
{
    __shared__ __align__(16) float HID[SS*MM];    // 1792
    __shared__ __align__(16) float SMD[SS*HH];    // 896
    __shared__ __align__(16) float PM[2*SS*HH];   // 1792
    __shared__ __align__(16) float PSN[SS*HH];    // 896
    __shared__ __align__(16) float PQ[SS*HH];     // 896
    __shared__ float red[16];
    int b = blockIdx.x, tid = threadIdx.x;

    for (int i = tid; i < SS*MM; i += 256) HID[i] = g_hid[b*SS*MM + i];
    for (int i = tid; i < SS*HH; i += 256) SMD[i] = g_smid[b*SS*HH + i];
    __syncthreads();

    {
        int part = tid >> 7, d = tid & 127;
        ull a[SS];
        #pragma unroll
        for (int s = 0; s < SS; s++) a[s] = 0ull;
        const float* wr = w2 + d*MM + part*128;
        const float* hr = HID + part*128;
        for (int k = 0; k < 32; k++) {
            ulonglong2 w = __ldg((const ulonglong2*)(wr + k*4));
            #pragma unroll
            for (int s = 0; s < SS; s++) {
                ulonglong2 xv = *(const ulonglong2*)(hr + s*MM + k*4);
                a[s] = ffma2(w.x, xv.x, ffma2(w.y, xv.y, a[s]));
            }
        }
        #pragma unroll
        for (int s = 0; s < SS; s++) PM[part*896 + s*128 + d] = hsum2(a[s]);
    }
    __syncthreads();

    for (int i = tid; i < SS*HH; i += 256) {
        float v = SMD[i] + PM[i] + PM[896+i] + b2[i & 127];
        SMD[i] = v;
        g_slots[b*SS*HH + i] = v;
        out[b*SS*HH + i] = v;
    }
    __syncthreads();

    prep_dev(b, tid, SMD, PSN, PQ, red,
             ln_s_g, ln_s_b, ln_in_g, ln_in_b, Wq, Wk);
}

// ---------------- launch ----------------
extern "C" void kernel_launch(void* const* d_in, const int* in_sizes, int n_in,
                              void* d_out, int out_size)
{
    const float* inputs     = (const float*)d_in[0];
    const float* slots_init = (const float*)d_in[1];
    const float* ln_in_g    = (const float*)d_in[2];
    const float* ln_in_b    = (const float*)d_in[3];
    const float* ln_s_g     = (const float*)d_in[4];
    const float* ln_s_b     = (const float*)d_in[5];
    const float* ln_m_g     = (const float*)d_in[6];
    const float* ln_m_b     = (const float*)d_in[7];
    const float* Wq         = (const float*)d_in[8];
    const float* Wk         = (const float*)d_in[9];
    const float* Wv         = (const float*)d_in[10];
    const float* W_ih       = (const float*)d_in[11];
    const float* W_hh       = (const float*)d_in[12];
    const float* b_ih       = (const float*)d_in[13];
    const float* b_hh       = (const float*)d_in[14];
    const float* mlp_w1     = (const float*)d_in[15];
    const float* mlp_b1     = (const float*)d_in[16];
    const float* mlp_w2     = (const float*)d_in[17];
    const float* mlp_b2     = (const float*)d_in[18];
    const float* slots_mu   = (const float*)d_in[19];
    const float* slots_lsig = (const float*)d_in[20];

    k_init0<<<BB, 128>>>(slots_init, slots_mu, slots_lsig,
                         ln_s_g, ln_s_b, ln_in_g, ln_in_b, Wq, Wk);

    for (int it = 0; it < 3; it++) {
        k_pass<<<dim3(NN/TROWS, BB), 128>>>(inputs);
        k_u1<<<dim3(BB, 4), 128>>>(ln_in_g, ln_in_b, Wv, W_hh, b_hh);
        k_u2<<<dim3(BB, 3), 128>>>(W_ih, b_ih);
        k_u3<<<dim3(BB, 2), 128>>>(ln_m_g, ln_m_b, mlp_w1, mlp_b1);
        k_u4<<<BB, 256>>>(ln_s_g, ln_s_b, ln_in_g, ln_in_b, Wq, Wk,
                          mlp_w2, mlp_b2, (float*)d_out);
    }
}

// round 15
// speedup vs baseline: 1.3657x; 1.3657x over previous
#include <cuda_runtime.h>
#include <math.h>

typedef unsigned long long ull;

#define BB 64
#define NN 4096
#define DD 128
#define SS 7
#define HH 128
#define MM 256
#define TROWS 128
#define LN_EPS 1e-5f
#define EPSF 1e-8f
#define SCALE 0.08838834764831845f   // 128^-0.5

// ---------------- device scratch ----------------
__device__ __align__(16) float g_slots[BB*SS*HH];
__device__ __align__(16) float g_u[BB*SS*DD];     // folded: SCALE*g*qk - e/128
__device__ float g_c[BB*SS];
__device__ __align__(16) float g_acc[BB*SS*DD];   // sum_n as*x
__device__ float g_sumWM[BB*SS];                  // sum_n as*m
__device__ float g_W[BB*SS];                      // sum_n ws

// transposed weights: T4[k4*J + j] = {W[j][4k4+0..3]}
__device__ __align__(16) float4 WvT4 [32*128];
__device__ __align__(16) float4 WihT4[32*384];
__device__ __align__(16) float4 WhhT4[32*384];
__device__ __align__(16) float4 w1T4 [32*256];
__device__ __align__(16) float4 w2T4 [64*128];
__device__ __align__(16) float4 WqT4 [32*128];

// ---------------- packed f32x2 helpers ----------------
static __device__ __forceinline__ ull pk2(float lo, float hi) {
    ull r; asm("mov.b64 %0,{%1,%2};" : "=l"(r) : "f"(lo), "f"(hi)); return r;
}
static __device__ __forceinline__ void upk2(float& lo, float& hi, ull v) {
    asm("mov.b64 {%0,%1},%2;" : "=f"(lo), "=f"(hi) : "l"(v));
}
static __device__ __forceinline__ ull ffma2(ull a, ull b, ull c) {
    ull d; asm("fma.rn.f32x2 %0,%1,%2,%3;" : "=l"(d) : "l"(a), "l"(b), "l"(c)); return d;
}
static __device__ __forceinline__ ull fadd2(ull a, ull b) {
    ull d; asm("add.rn.f32x2 %0,%1,%2;" : "=l"(d) : "l"(a), "l"(b)); return d;
}
static __device__ __forceinline__ float hsum2(ull v) {
    float lo, hi; upk2(lo, hi, v); return lo + hi;
}
static __device__ __forceinline__ float dot4(float4 a, float4 b) {
    return a.x*b.x + a.y*b.y + a.z*b.z + a.w*b.w;
}

// GEMV with transposed weights: res[s] = sum_k Xs[s][k] * W[j][k]
// Wt[k4*J + j] coalesced across j; Xs broadcast from smem.
template<int J, int K4>
static __device__ __forceinline__ void gemvT(const float4* __restrict__ Wt,
                                             const float* Xs, int xstr,
                                             int j, float* res)
{
    ull a[SS];
    #pragma unroll
    for (int s = 0; s < SS; s++) a[s] = 0ull;
    #pragma unroll 4
    for (int k4 = 0; k4 < K4; k4++) {
        ulonglong2 wv = __ldg((const ulonglong2*)(Wt + k4*J + j));
        #pragma unroll
        for (int s = 0; s < SS; s++) {
            ulonglong2 xv = *(const ulonglong2*)&Xs[s*xstr + k4*4];
            a[s] = ffma2(wv.x, xv.x, ffma2(wv.y, xv.y, a[s]));
        }
    }
    #pragma unroll
    for (int s = 0; s < SS; s++) res[s] = hsum2(a[s]);
}

// ---------------- weight transpose (once) ----------------
__global__ void __launch_bounds__(256) k_tr(
    const float* __restrict__ Wv,  const float* __restrict__ Wih,
    const float* __restrict__ Whh, const float* __restrict__ w1,
    const float* __restrict__ w2,  const float* __restrict__ Wq)
{
    int y = blockIdx.y;
    int idx = blockIdx.x*256 + threadIdx.x;
    const float* src; float4* dst; int J, K4;
    if      (y == 0) { src = Wv;  dst = WvT4;  J = 128; K4 = 32; }
    else if (y == 1) { src = Wih; dst = WihT4; J = 384; K4 = 32; }
    else if (y == 2) { src = Whh; dst = WhhT4; J = 384; K4 = 32; }
    else if (y == 3) { src = w1;  dst = w1T4;  J = 256; K4 = 32; }
    else if (y == 4) { src = w2;  dst = w2T4;  J = 128; K4 = 64; }
    else             { src = Wq;  dst = WqT4;  J = 128; K4 = 32; }
    int n = J*K4;
    if (idx >= n) return;
    int k4 = idx / J, j = idx - k4*J;
    int K = K4*4;
    dst[idx] = make_float4(src[j*K + 4*k4 + 0], src[j*K + 4*k4 + 1],
                           src[j*K + 4*k4 + 2], src[j*K + 4*k4 + 3]);
}

// ---------------- prep (device): slot LN -> q -> qk -> u~,c; zero accs ----
static __device__ void prep_dev(
    int b, int tid,
    const float* slots_sm,
    float* sn, float* q, float* red,
    const float* __restrict__ ln_s_g, const float* __restrict__ ln_s_b,
    const float* __restrict__ ln_in_g, const float* __restrict__ ln_in_b,
    const float* __restrict__ Wk)
{
    int wid = tid >> 5, lane = tid & 31;
    if (tid < 16) red[tid] = 0.f;
    __syncthreads();

    if (tid < 128) {
        for (int s = wid; s < SS; s += 4) {
            float4 x = *(const float4*)&slots_sm[s*HH + lane*4];
            float sm = x.x+x.y+x.z+x.w;
            float sq = dot4(x, x);
            #pragma unroll
            for (int o = 16; o; o >>= 1) {
                sm += __shfl_xor_sync(0xffffffffu, sm, o);
                sq += __shfl_xor_sync(0xffffffffu, sq, o);
            }
            float m   = sm * (1.f/HH);
            float inv = rsqrtf(sq*(1.f/HH) - m*m + LN_EPS);
            int d = lane*4;
            sn[s*HH+d+0] = (x.x-m)*inv*ln_s_g[d+0] + ln_s_b[d+0];
            sn[s*HH+d+1] = (x.y-m)*inv*ln_s_g[d+1] + ln_s_b[d+1];
            sn[s*HH+d+2] = (x.z-m)*inv*ln_s_g[d+2] + ln_s_b[d+2];
            sn[s*HH+d+3] = (x.w-m)*inv*ln_s_g[d+3] + ln_s_b[d+3];
        }
    }
    __syncthreads();

    // q[s][h] = sn[s] . Wq[h]  (transposed-coalesced)
    if (tid < 128) {
        float a7[SS];
        gemvT<128,32>(WqT4, sn, HH, tid, a7);
        #pragma unroll
        for (int s = 0; s < SS; s++) q[s*HH+tid] = a7[s];
    }
    __syncthreads();

    float acc[SS];
    if (tid < 128) {
        int d = tid;
        #pragma unroll
        for (int s = 0; s < SS; s++) acc[s] = 0.f;
        for (int h4 = 0; h4 < HH/4; h4++) {
            float w0 = __ldg(&Wk[(h4*4+0)*HH + d]);
            float w1v = __ldg(&Wk[(h4*4+1)*HH + d]);
            float w2v = __ldg(&Wk[(h4*4+2)*HH + d]);
            float w3 = __ldg(&Wk[(h4*4+3)*HH + d]);
            #pragma unroll
            for (int s = 0; s < SS; s++) {
                float4 qv = *(const float4*)&q[s*HH + h4*4];
                acc[s] += qv.x*w0 + qv.y*w1v + qv.z*w2v + qv.w*w3;
            }
        }
        float gg  = ln_in_g[d];
        float bbv = ln_in_b[d];
        float pe[SS], pc[SS];
        #pragma unroll
        for (int s = 0; s < SS; s++) {
            pe[s] = SCALE * gg  * acc[s];
            pc[s] = SCALE * bbv * acc[s];
        }
        #pragma unroll
        for (int o = 16; o; o >>= 1) {
            #pragma unroll
            for (int s = 0; s < SS; s++) {
                pe[s] += __shfl_xor_sync(0xffffffffu, pe[s], o);
                pc[s] += __shfl_xor_sync(0xffffffffu, pc[s], o);
            }
        }
        if (lane == 0) {
            #pragma unroll
            for (int s = 0; s < SS; s++) {
                atomicAdd(&red[s],   pe[s]);
                atomicAdd(&red[8+s], pc[s]);
            }
        }
    }
    __syncthreads();

    if (tid < 128) {
        int d = tid;
        float gg = ln_in_g[d];
        #pragma unroll
        for (int s = 0; s < SS; s++)
            g_u[(b*SS+s)*DD + d] = SCALE*gg*acc[s] - red[s]*(1.f/DD);
    }
    if (tid < SS) {
        g_c[b*SS+tid]     = red[8+tid];
        g_W[b*SS+tid]     = 0.f;
        g_sumWM[b*SS+tid] = 0.f;
    }
    for (int i = tid; i < SS*DD; i += blockDim.x) g_acc[b*SS*DD + i] = 0.f;
}

// ---------------- init + first prep ----------------
__global__ void __launch_bounds__(128) k_init0(
    const float* __restrict__ sinit,
    const float* __restrict__ mu,
    const float* __restrict__ lsig,
    const float* __restrict__ ln_s_g, const float* __restrict__ ln_s_b,
    const float* __restrict__ ln_in_g, const float* __restrict__ ln_in_b,
    const float* __restrict__ Wk)
{
    __shared__ __align__(16) float T[896*3];
    __shared__ float red[16];
    int b = blockIdx.x, tid = threadIdx.x;
    for (int i = tid; i < SS*HH; i += 128) {
        int s = i >> 7, h = i & 127;
        float v = mu[h] + expf(lsig[h]) * sinit[(b*SS+s)*(HH+4) + h];
        T[i] = v;
        g_slots[b*SS*HH + i] = v;
    }
    __syncthreads();
    prep_dev(b, tid, T, T+896, T+1792, red,
             ln_s_g, ln_s_b, ln_in_g, ln_in_b, Wk);
}

// ---------------- streaming pass (R6-proven): 128-row tile, two-pass -----
__global__ void __launch_bounds__(256) k_pass(const float* __restrict__ inputs)
{
    extern __shared__ float smd[];
    float* tile = smd;                        // TROWS * 132
    float* ubuf = smd + TROWS*132;            // 7*128
    ull*   wbuf = (ull*)(smd + TROWS*132 + 896);   // TROWS*9 ull
    float* sAW  = smd + TROWS*132 + 896 + TROWS*9*2;  // 7
    float* sAM  = sAW + 7;                    // 7

    int b = blockIdx.y, chunk = blockIdx.x;
    int tid = threadIdx.x, wid = tid >> 5, lane = tid & 31;

    if (tid < 224)
        ((float4*)ubuf)[tid] = ((const float4*)(g_u + b*SS*DD))[tid];
    if (tid < 14) { if (tid < 7) sAW[tid] = 0.f; else sAM[tid-7] = 0.f; }

    const float4* gin = (const float4*)(inputs + ((size_t)b*NN + (size_t)chunk*TROWS)*DD);
    #pragma unroll
    for (int j = 0; j < TROWS*32/256; j++) {
        int i = tid + j*256;
        int r = i >> 5, c = i & 31;
        *(float4*)&tile[r*132 + c*4] = __ldg(&gin[i]);
    }
    __syncthreads();

    // pass 1: thread = row (threads 0..127)
    if (tid < TROWS) {
        const float* xr = tile + tid*132;
        ull d2[SS], sm2 = 0ull, sq2 = 0ull;
        #pragma unroll
        for (int s = 0; s < SS; s++) d2[s] = 0ull;
        for (int k = 0; k < 32; k++) {
            ulonglong2 x = *(const ulonglong2*)(xr + k*4);
            sm2 = fadd2(sm2, x.x);
            sm2 = fadd2(sm2, x.y);
            sq2 = ffma2(x.x, x.x, sq2);
            sq2 = ffma2(x.y, x.y, sq2);
            #pragma unroll
            for (int s = 0; s < SS; s++) {
                ulonglong2 u = *(const ulonglong2*)&ubuf[s*128 + k*4];
                d2[s] = ffma2(x.x, u.x, d2[s]);
                d2[s] = ffma2(x.y, u.y, d2[s]);
            }
        }
        float m   = hsum2(sm2) * (1.f/DD);
        float inv = rsqrtf(hsum2(sq2)*(1.f/DD) - m*m + LN_EPS);
        float lg[SS], mx = -1e30f;
        #pragma unroll
        for (int s = 0; s < SS; s++) {
            lg[s] = hsum2(d2[s])*inv + __ldg(&g_c[b*SS+s]);
            mx = fmaxf(mx, lg[s]);
        }
        float w[SS], sum = 0.f;
        #pragma unroll
        for (int s = 0; s < SS; s++) { w[s] = __expf(lg[s]-mx); sum += w[s]; }
        float isum = __fdividef(1.f, sum);
        float pw[SS], pm[SS];
        #pragma unroll
        for (int s = 0; s < SS; s++) {
            float ws = w[s]*isum + EPSF;
            float as = ws*inv;
            wbuf[tid*9 + s] = pk2(as, as);
            pw[s] = ws;
            pm[s] = as*m;
        }
        #pragma unroll
        for (int o = 16; o; o >>= 1) {
            #pragma unroll
            for (int s = 0; s < SS; s++) {
                pw[s] += __shfl_xor_sync(0xffffffffu, pw[s], o);
                pm[s] += __shfl_xor_sync(0xffffffffu, pm[s], o);
            }
        }
        if (lane == 0) {
            #pragma unroll
            for (int s = 0; s < SS; s++) {
                atomicAdd(&sAW[s], pw[s]);
                atomicAdd(&sAM[s], pm[s]);
            }
        }
    }
    __syncthreads();

    // pass 2: warp per 16 rows, lanes = d
    ull acc[SS][2];
    #pragma unroll
    for (int s = 0; s < SS; s++) { acc[s][0] = 0ull; acc[s][1] = 0ull; }
    {
        int r0 = wid * (TROWS/8);
        #pragma unroll 4
        for (int i = 0; i < TROWS/8; i++) {
            int r = r0 + i;
            ulonglong2 x = *(const ulonglong2*)&tile[r*132 + lane*4];
            #pragma unroll
            for (int s = 0; s < SS; s++) {
                ull a = wbuf[r*9 + s];
                acc[s][0] = ffma2(x.x, a, acc[s][0]);
                acc[s][1] = ffma2(x.y, a, acc[s][1]);
            }
        }
    }
    __syncthreads();            // tile no longer needed
    float* red = tile;          // [7][8][128]
    #pragma unroll
    for (int s = 0; s < SS; s++) {
        float4 v;
        upk2(v.x, v.y, acc[s][0]);
        upk2(v.z, v.w, acc[s][1]);
        *(float4*)&red[(s*8+wid)*128 + lane*4] = v;
    }
    __syncthreads();
    if (tid < SS*32) {
        int s = tid >> 5, l = tid & 31;
        float4 t = make_float4(0.f,0.f,0.f,0.f);
        #pragma unroll
        for (int w = 0; w < 8; w++) {
            float4 r = *(const float4*)&red[(s*8+w)*128 + l*4];
            t.x += r.x; t.y += r.y; t.z += r.z; t.w += r.w;
        }
        float* dst = &g_acc[(b*SS+s)*DD + l*4];
        atomicAdd(dst+0, t.x); atomicAdd(dst+1, t.y);
        atomicAdd(dst+2, t.z); atomicAdd(dst+3, t.w);
    }
    if (tid < 2*SS) {
        if (tid < SS) atomicAdd(&g_W[b*SS+tid],        sAW[tid]);
        else          atomicAdd(&g_sumWM[b*SS+tid-SS], sAM[tid-SS]);
    }
}

// ---------------- fused update: coalesced GEMV-T chain + prep ------------
__global__ void __launch_bounds__(512) k_upd(
    const float* __restrict__ ln_in_g, const float* __restrict__ ln_in_b,
    const float* __restrict__ ln_m_g,  const float* __restrict__ ln_m_b,
    const float* __restrict__ ln_s_g,  const float* __restrict__ ln_s_b,
    const float* __restrict__ Wk,
    const float* __restrict__ b_ih, const float* __restrict__ b_hh,
    const float* __restrict__ b1,   const float* __restrict__ b2,
    float* __restrict__ out)
{
    __shared__ __align__(16) float SP [896];
    __shared__ __align__(16) float Y  [896];
    __shared__ __align__(16) float UPD[896];
    __shared__ __align__(16) float GI [2688];
    __shared__ __align__(16) float GH [2688];
    __shared__ __align__(16) float SMD[896];
    __shared__ __align__(16) float SNM[896];
    __shared__ __align__(16) float HID[1792];
    __shared__ float Ws[SS], SWM[SS], red[16];

    int b = blockIdx.x, tid = threadIdx.x, wid = tid >> 5, lane = tid & 31;

    // ph1: y + load prev slots
    if (tid < SS) Ws[tid] = g_W[b*SS+tid];
    else if (tid < 2*SS) SWM[tid-SS] = g_sumWM[b*SS+tid-SS];
    __syncthreads();
    for (int i = tid; i < SS*HH; i += 512) {
        SP[i] = g_slots[b*SS*HH + i];
        int s = i >> 7, d = i & 127;
        float wv = Ws[s];
        Y[i] = (ln_in_g[d]*(g_acc[b*SS*DD+i] - SWM[s]) + ln_in_b[d]*wv)
               * __fdividef(1.f, wv);
    }
    __syncthreads();

    // ph2: warps 0-3 -> Wv ; warps 4-15 -> gh
    if (tid < 128) {
        float a7[SS];
        gemvT<128,32>(WvT4, Y, 128, tid, a7);
        #pragma unroll
        for (int s = 0; s < SS; s++) UPD[s*128 + tid] = a7[s];
    } else {
        int r = tid - 128;
        float a7[SS];
        gemvT<384,32>(WhhT4, SP, 128, r, a7);
        float bh = b_hh[r];
        #pragma unroll
        for (int s = 0; s < SS; s++) GH[s*384 + r] = a7[s] + bh;
    }
    __syncthreads();

    // ph3: gi
    if (tid < 384) {
        float a7[SS];
        gemvT<384,32>(WihT4, UPD, 128, tid, a7);
        float bi = b_ih[tid];
        #pragma unroll
        for (int s = 0; s < SS; s++) GI[s*384 + tid] = a7[s] + bi;
    }
    __syncthreads();

    // ph4: GRU -> SMD
    for (int i = tid; i < SS*HH; i += 512) {
        int s = i >> 7, h = i & 127;
        float gr = GI[s*384 + h]       + GH[s*384 + h];
        float gz = GI[s*384 + 128 + h] + GH[s*384 + 128 + h];
        float rr = 1.f/(1.f + __expf(-gr));
        float zz = 1.f/(1.f + __expf(-gz));
        float nn = tanhf(GI[s*384 + 256 + h] + rr*GH[s*384 + 256 + h]);
        SMD[i] = (1.f - zz)*nn + zz*SP[i];
    }
    __syncthreads();

    // ph5: LayerNorm(ln_m) -> SNM
    if (wid < SS) {
        float4 x = *(const float4*)&SMD[wid*HH + lane*4];
        float sm = x.x+x.y+x.z+x.w;
        float sq = dot4(x, x);
        #pragma unroll
        for (int o = 16; o; o >>= 1) {
            sm += __shfl_xor_sync(0xffffffffu, sm, o);
            sq += __shfl_xor_sync(0xffffffffu, sq, o);
        }
        float m   = sm * (1.f/HH);
        float inv = rsqrtf(sq*(1.f/HH) - m*m + LN_EPS);
        int d = lane*4;
        SNM[wid*HH+d+0] = (x.x-m)*inv*ln_m_g[d+0] + ln_m_b[d+0];
        SNM[wid*HH+d+1] = (x.y-m)*inv*ln_m_g[d+1] + ln_m_b[d+1];
        SNM[wid*HH+d+2] = (x.z-m)*inv*ln_m_g[d+2] + ln_m_b[d+2];
        SNM[wid*HH+d+3] = (x.w-m)*inv*ln_m_g[d+3] + ln_m_b[d+3];
    }
    __syncthreads();

    // ph6: MLP1
    if (tid < 256) {
        float a7[SS];
        gemvT<256,32>(w1T4, SNM, 128, tid, a7);
        float bb = b1[tid];
        #pragma unroll
        for (int s = 0; s < SS; s++)
            HID[s*MM + tid] = fmaxf(a7[s] + bb, 0.f);
    }
    __syncthreads();

    // ph7: MLP2 + residual -> final slots
    if (tid < 128) {
        float a7[SS];
        gemvT<128,64>(w2T4, HID, 256, tid, a7);
        float bb = b2[tid];
        #pragma unroll
        for (int s = 0; s < SS; s++) {
            float v = SMD[s*128 + tid] + a7[s] + bb;
            SMD[s*128 + tid] = v;
            g_slots[b*SS*HH + s*128 + tid] = v;
            out[b*SS*HH + s*128 + tid] = v;
        }
    }
    __syncthreads();

    // ph8: prep next iteration (Y, SNM are dead -> scratch)
    prep_dev(b, tid, SMD, Y, SNM, red,
             ln_s_g, ln_s_b, ln_in_g, ln_in_b, Wk);
}

// ---------------- launch ----------------
extern "C" void kernel_launch(void* const* d_in, const int* in_sizes, int n_in,
                              void* d_out, int out_size)
{
    const float* inputs     = (const float*)d_in[0];
    const float* slots_init = (const float*)d_in[1];
    const float* ln_in_g    = (const float*)d_in[2];
    const float* ln_in_b    = (const float*)d_in[3];
    const float* ln_s_g     = (const float*)d_in[4];
    const float* ln_s_b     = (const float*)d_in[5];
    const float* ln_m_g     = (const float*)d_in[6];
    const float* ln_m_b     = (const float*)d_in[7];
    const float* Wq         = (const float*)d_in[8];
    const float* Wk         = (const float*)d_in[9];
    const float* Wv         = (const float*)d_in[10];
    const float* W_ih       = (const float*)d_in[11];
    const float* W_hh       = (const float*)d_in[12];
    const float* b_ih       = (const float*)d_in[13];
    const float* b_hh       = (const float*)d_in[14];
    const float* mlp_w1     = (const float*)d_in[15];
    const float* mlp_b1     = (const float*)d_in[16];
    const float* mlp_w2     = (const float*)d_in[17];
    const float* mlp_b2     = (const float*)d_in[18];
    const float* slots_mu   = (const float*)d_in[19];
    const float* slots_lsig = (const float*)d_in[20];

    const int pass_smem = (TROWS*132 + 896 + TROWS*9*2 + 16) * 4;
    cudaFuncSetAttribute(k_pass, cudaFuncAttributeMaxDynamicSharedMemorySize,
                         pass_smem);

    k_tr<<<dim3(48, 6), 256>>>(Wv, W_ih, W_hh, mlp_w1, mlp_w2, Wq);
    k_init0<<<BB, 128>>>(slots_init, slots_mu, slots_lsig,
                         ln_s_g, ln_s_b, ln_in_g, ln_in_b, Wk);

    for (int it = 0; it < 3; it++) {
        k_pass<<<dim3(NN/TROWS, BB), 256, pass_smem>>>(inputs);
        k_upd<<<BB, 512>>>(ln_in_g, ln_in_b, ln_m_g, ln_m_b,
                           ln_s_g, ln_s_b, Wk,
                           b_ih, b_hh, mlp_b1, mlp_b2,
                           (float*)d_out);
    }
}